// round 4
// baseline (speedup 1.0000x reference)
#include <cuda_runtime.h>
#include <math.h>

#define NN 100000
#define DD 128
#define HH 64
#define CC 40
#define NB 391          // ceil(NN/256) scan blocks

// ---- scratch (__device__ globals per harness rules) ----
__device__ float g_y1[(size_t)NN * HH];     // x @ W1l            25.6 MB
__device__ float g_self[(size_t)NN * HH];   // x @ W1r + b1       25.6 MB
__device__ float g_h[(size_t)NN * HH];      // layer-1 output     25.6 MB
__device__ float g_z[(size_t)NN * 80];      // [z_l | z_r+b2]     32.0 MB
__device__ int   g_cnt[NN];
__device__ int   g_rowptr[NN];
__device__ int   g_cur[NN];
__device__ float g_invdeg[NN];
__device__ int   g_srcs[2000000];
__device__ int   g_exc[NB * 256];
__device__ int   g_bsum[512];
__device__ int   g_boff[512];
__device__ int   g_is64;

// ---------------------------------------------------------------------------
__global__ void k_detect(const void* __restrict__ ei) {
    const long long* p = (const long long*)ei;
    int ok = 1;
    for (int i = 0; i < 128; ++i) {
        long long v = p[i];
        if (v < 0 || v >= NN) { ok = 0; break; }
    }
    g_is64 = ok;
}

__global__ void k_zero_cnt() {
    int i = blockIdx.x * blockDim.x + threadIdx.x;
    if (i < NN) g_cnt[i] = 0;
}

__global__ void k_hist(const void* __restrict__ ei, int nE) {
    int e = blockIdx.x * blockDim.x + threadIdx.x;
    if (e >= nE) return;
    int d = g_is64 ? (int)((const long long*)ei)[nE + e]
                   : ((const int*)ei)[nE + e];
    atomicAdd(&g_cnt[d], 1);
}

__global__ void k_scan1() {
    __shared__ int sh[256];
    int t = threadIdx.x, b = blockIdx.x;
    int i = b * 256 + t;
    int v = (i < NN) ? g_cnt[i] : 0;
    sh[t] = v;
    __syncthreads();
    #pragma unroll
    for (int off = 1; off < 256; off <<= 1) {
        int u = (t >= off) ? sh[t - off] : 0;
        __syncthreads();
        sh[t] += u;
        __syncthreads();
    }
    if (i < NN) g_exc[i] = sh[t] - v;
    if (t == 255) g_bsum[b] = sh[t];
}

__global__ void k_scan2() {
    __shared__ int sh[512];
    int t = threadIdx.x;
    int v = (t < NB) ? g_bsum[t] : 0;
    sh[t] = v;
    __syncthreads();
    #pragma unroll
    for (int off = 1; off < 512; off <<= 1) {
        int u = (t >= off) ? sh[t - off] : 0;
        __syncthreads();
        sh[t] += u;
        __syncthreads();
    }
    g_boff[t] = sh[t] - v;
}

__global__ void k_scan3() {
    int i = blockIdx.x * blockDim.x + threadIdx.x;
    if (i >= NN) return;
    int row = g_exc[i] + g_boff[i >> 8];
    g_rowptr[i] = row;
    g_cur[i] = row;
    g_invdeg[i] = 1.0f / fmaxf((float)g_cnt[i], 1.0f);
}

__global__ void k_fill(const void* __restrict__ ei, int nE) {
    int e = blockIdx.x * blockDim.x + threadIdx.x;
    if (e >= nE) return;
    int s, d;
    if (g_is64) {
        const long long* p = (const long long*)ei;
        s = (int)p[e]; d = (int)p[nE + e];
    } else {
        const int* p = (const int*)ei;
        s = p[e]; d = p[nE + e];
    }
    int pos = atomicAdd(&g_cur[d], 1);
    g_srcs[pos] = s;
}

// ---------------------------------------------------------------------------
// GEMM1: [y1 | self+b1] = x[N,128] @ [W1l | W1r][128,128]
// Tile: 64 rows x 128 cols, K-chunk 32, 256 threads, 4x8 microtile.
// A smem transposed [k][m], pitch 65 (store-conflict-free); A read as
// 4 scalar LDS (broadcast within quarter-warp) -- NO float4 on pitch-65 rows.
// ---------------------------------------------------------------------------
__global__ void k_gemm1(const float* __restrict__ x,
                        const float* __restrict__ Wl,
                        const float* __restrict__ Wr,
                        const float* __restrict__ b) {
    __shared__ float As[32][65];
    __shared__ float Bs[32][128];

    int tid = threadIdx.x;
    int tx = tid & 15;        // col group: 8 cols
    int ty = tid >> 4;        // row group: 4 rows
    int m0 = blockIdx.x * 64;

    float acc[4][8] = {};

    #pragma unroll 1
    for (int c = 0; c < 4; ++c) {
        int kb = c * 32;
        __syncthreads();
        // load A: 64 rows x 32 k ; thread: 2 rows x 4 k (2 float4 gmem loads)
        {
            int kk = (tid & 7) * 4;
            int m  = tid >> 3;                 // 0..31
            #pragma unroll
            for (int r = 0; r < 2; ++r, m += 32) {
                int mg = min(m0 + m, NN - 1);
                float4 v = __ldg((const float4*)(x + (size_t)mg * DD + kb + kk));
                As[kk + 0][m] = v.x;
                As[kk + 1][m] = v.y;
                As[kk + 2][m] = v.z;
                As[kk + 3][m] = v.w;
            }
        }
        // load B: 32 k-rows x 128 cols ; thread: 1 row x 16 cols (4 float4)
        {
            int k = tid >> 3;                  // 0..31
            int n = (tid & 7) * 16;            // 0,16,...,112
            const float* W = (n < 64) ? (Wl + (size_t)(kb + k) * 64 + n)
                                      : (Wr + (size_t)(kb + k) * 64 + (n - 64));
            float4 v0 = __ldg((const float4*)(W));
            float4 v1 = __ldg((const float4*)(W + 4));
            float4 v2 = __ldg((const float4*)(W + 8));
            float4 v3 = __ldg((const float4*)(W + 12));
            *(float4*)&Bs[k][n]      = v0;
            *(float4*)&Bs[k][n + 4]  = v1;
            *(float4*)&Bs[k][n + 8]  = v2;
            *(float4*)&Bs[k][n + 12] = v3;
        }
        __syncthreads();
        #pragma unroll
        for (int k = 0; k < 32; ++k) {
            float av[4];
            av[0] = As[k][ty * 4 + 0];
            av[1] = As[k][ty * 4 + 1];
            av[2] = As[k][ty * 4 + 2];
            av[3] = As[k][ty * 4 + 3];
            float4 b0 = *(float4*)&Bs[k][tx * 8];
            float4 b1 = *(float4*)&Bs[k][tx * 8 + 4];
            #pragma unroll
            for (int i = 0; i < 4; ++i) {
                acc[i][0] += av[i] * b0.x; acc[i][1] += av[i] * b0.y;
                acc[i][2] += av[i] * b0.z; acc[i][3] += av[i] * b0.w;
                acc[i][4] += av[i] * b1.x; acc[i][5] += av[i] * b1.y;
                acc[i][6] += av[i] * b1.z; acc[i][7] += av[i] * b1.w;
            }
        }
    }

    // epilogue: cols 0..63 -> g_y1 ; cols 64..127 -> g_self (+b1)
    int n = tx * 8;
    bool isSelf = (n >= 64);
    float bb[8];
    #pragma unroll
    for (int j = 0; j < 8; ++j) bb[j] = isSelf ? b[n - 64 + j] : 0.f;
    float* dst = isSelf ? g_self : g_y1;
    int nc = isSelf ? (n - 64) : n;
    #pragma unroll
    for (int i = 0; i < 4; ++i) {
        int mg = m0 + ty * 4 + i;
        if (mg < NN) {
            float4 o0, o1;
            o0.x = acc[i][0] + bb[0]; o0.y = acc[i][1] + bb[1];
            o0.z = acc[i][2] + bb[2]; o0.w = acc[i][3] + bb[3];
            o1.x = acc[i][4] + bb[4]; o1.y = acc[i][5] + bb[5];
            o1.z = acc[i][6] + bb[6]; o1.w = acc[i][7] + bb[7];
            *(float4*)(dst + (size_t)mg * HH + nc)     = o0;
            *(float4*)(dst + (size_t)mg * HH + nc + 4) = o1;
        }
    }
}

// ---------------------------------------------------------------------------
// agg1 + ReLU: h[n] = relu( invdeg * sum_{s} y1[s] + self[n] )
// warp per node, lane -> float2 (64 floats per row).
// ---------------------------------------------------------------------------
__global__ void k_agg1(void) {
    int w = (blockIdx.x * blockDim.x + threadIdx.x) >> 5;
    int lane = threadIdx.x & 31;
    if (w >= NN) return;
    int beg = g_rowptr[w], n = g_cnt[w];
    const float2* yb = (const float2*)g_y1;
    float2 a0 = make_float2(0.f, 0.f), a1 = make_float2(0.f, 0.f);
    int e = 0;
    for (; e + 1 < n; e += 2) {
        int s0 = g_srcs[beg + e];
        int s1 = g_srcs[beg + e + 1];
        float2 v0 = __ldg(yb + (size_t)s0 * 32 + lane);
        float2 v1 = __ldg(yb + (size_t)s1 * 32 + lane);
        a0.x += v0.x; a0.y += v0.y;
        a1.x += v1.x; a1.y += v1.y;
    }
    if (e < n) {
        int s0 = g_srcs[beg + e];
        float2 v0 = __ldg(yb + (size_t)s0 * 32 + lane);
        a0.x += v0.x; a0.y += v0.y;
    }
    float sc = g_invdeg[w];
    float2 s = ((const float2*)g_self)[(size_t)w * 32 + lane];
    float2 o;
    o.x = fmaxf((a0.x + a1.x) * sc + s.x, 0.f);
    o.y = fmaxf((a0.y + a1.y) * sc + s.y, 0.f);
    ((float2*)g_h)[(size_t)w * 32 + lane] = o;
}

// ---------------------------------------------------------------------------
// GEMM2: g_z[n][0..39] = h[n] @ W2l ; g_z[n][40..79] = h[n] @ W2r + b2
// warp per node.
// ---------------------------------------------------------------------------
__global__ void k_gemm2(const float* __restrict__ Wl,
                        const float* __restrict__ Wr,
                        const float* __restrict__ b) {
    __shared__ float sWl[64 * 40];
    __shared__ float sWr[64 * 40];
    __shared__ float sb[40];
    int tid = threadIdx.x;
    for (int i = tid; i < 64 * 40; i += blockDim.x) { sWl[i] = Wl[i]; sWr[i] = Wr[i]; }
    if (tid < 40) sb[tid] = b[tid];
    __syncthreads();

    int w = (blockIdx.x * blockDim.x + tid) >> 5;
    int lane = tid & 31;
    if (w >= NN) return;

    const float* hr = g_h + (size_t)w * HH;
    float h0 = hr[lane], h1 = hr[lane + 32];

    float zl0 = 0.f, zl1 = 0.f, zr0 = 0.f, zr1 = 0.f;
    #pragma unroll
    for (int k = 0; k < 32; ++k) {
        float hv = __shfl_sync(0xffffffffu, h0, k);
        zl0 += hv * sWl[k * 40 + lane];
        zr0 += hv * sWr[k * 40 + lane];
        if (lane < 8) {
            zl1 += hv * sWl[k * 40 + 32 + lane];
            zr1 += hv * sWr[k * 40 + 32 + lane];
        }
    }
    #pragma unroll
    for (int k = 0; k < 32; ++k) {
        float hv = __shfl_sync(0xffffffffu, h1, k);
        int kr = k + 32;
        zl0 += hv * sWl[kr * 40 + lane];
        zr0 += hv * sWr[kr * 40 + lane];
        if (lane < 8) {
            zl1 += hv * sWl[kr * 40 + 32 + lane];
            zr1 += hv * sWr[kr * 40 + 32 + lane];
        }
    }

    float* zrow = g_z + (size_t)w * 80;
    zrow[lane] = zl0;
    zrow[40 + lane] = zr0 + sb[lane];
    if (lane < 8) {
        zrow[32 + lane] = zl1;
        zrow[72 + lane] = zr1 + sb[32 + lane];
    }
}

// ---------------------------------------------------------------------------
// final: out[n] = log_softmax( invdeg * sum_s z_l[s] + z_r[n] )
// warp per node; lane covers col lane, lanes 0..7 also col 32+lane.
// ---------------------------------------------------------------------------
__global__ void k_final(float* __restrict__ out) {
    int w = (blockIdx.x * blockDim.x + threadIdx.x) >> 5;
    int lane = threadIdx.x & 31;
    if (w >= NN) return;
    int beg = g_rowptr[w], n = g_cnt[w];

    float a0 = 0.f, a1 = 0.f;
    bool lo8 = (lane < 8);
    for (int e = 0; e < n; ++e) {
        int s = g_srcs[beg + e];
        const float* zr = g_z + (size_t)s * 80;
        a0 += __ldg(zr + lane);
        if (lo8) a1 += __ldg(zr + 32 + lane);
    }
    float sc = g_invdeg[w];
    const float* zme = g_z + (size_t)w * 80;
    float z0 = a0 * sc + zme[40 + lane];
    float z1 = lo8 ? (a1 * sc + zme[72 + lane]) : -INFINITY;

    float m = fmaxf(z0, z1);
    #pragma unroll
    for (int o = 16; o; o >>= 1) m = fmaxf(m, __shfl_xor_sync(0xffffffffu, m, o));
    float e = expf(z0 - m) + (lo8 ? expf(z1 - m) : 0.f);
    #pragma unroll
    for (int o = 16; o; o >>= 1) e += __shfl_xor_sync(0xffffffffu, e, o);
    float lse = logf(e) + m;

    out[(size_t)w * CC + lane] = z0 - lse;
    if (lo8) out[(size_t)w * CC + 32 + lane] = z1 - lse;
}

// ---------------------------------------------------------------------------
extern "C" void kernel_launch(void* const* d_in, const int* in_sizes, int n_in,
                              void* d_out, int out_size) {
    const float* x   = (const float*)d_in[0];
    const void*  ei  = d_in[1];
    const float* W1l = (const float*)d_in[2];
    const float* W1r = (const float*)d_in[3];
    const float* b1  = (const float*)d_in[4];
    const float* W2l = (const float*)d_in[5];
    const float* W2r = (const float*)d_in[6];
    const float* b2  = (const float*)d_in[7];
    float* out = (float*)d_out;

    int nE = in_sizes[1] / 2;
    int eBlocks = (nE + 255) / 256;
    int nWarpBlocks = (NN * 32 + 255) / 256;

    k_detect<<<1, 1>>>(ei);
    k_zero_cnt<<<(NN + 255) / 256, 256>>>();
    k_hist<<<eBlocks, 256>>>(ei, nE);
    k_scan1<<<NB, 256>>>();
    k_scan2<<<1, 512>>>();
    k_scan3<<<(NN + 255) / 256, 256>>>();
    k_fill<<<eBlocks, 256>>>(ei, nE);

    k_gemm1<<<(NN + 63) / 64, 256>>>(x, W1l, W1r, b1);
    k_agg1<<<nWarpBlocks, 256>>>();
    k_gemm2<<<(NN + 7) / 8, 256>>>(W2l, W2r, b2);
    k_final<<<nWarpBlocks, 256>>>(out);
}

// round 5
// speedup vs baseline: 1.0208x; 1.0208x over previous
#include <cuda_runtime.h>
#include <math.h>

#define NN 100000
#define DD 128
#define HH 64
#define CC 40
#define NB 391          // ceil(NN/256) scan blocks

typedef unsigned long long u64;

// ---- scratch (__device__ globals per harness rules) ----
__device__ float g_y1[(size_t)NN * HH];     // x @ W1l            25.6 MB
__device__ float g_self[(size_t)NN * HH];   // x @ W1r + b1       25.6 MB
__device__ float g_h[(size_t)NN * HH];      // layer-1 output     25.6 MB
__device__ float g_agg2[(size_t)NN * HH];   // mean(h[nbrs])      25.6 MB
__device__ int   g_cnt[NN];
__device__ int   g_rowptr[NN];
__device__ int   g_cur[NN];
__device__ float g_invdeg[NN];
__device__ int   g_srcs[2000000];
__device__ int   g_exc[NB * 256];
__device__ int   g_bsum[512];
__device__ int   g_boff[512];
__device__ int   g_is64;

// ---- f32x2 packed-math helpers (sm_103a FFMA2) ----
__device__ __forceinline__ u64 pack2(float lo, float hi) {
    u64 r;
    asm("mov.b64 %0, {%1, %2};" : "=l"(r) : "f"(lo), "f"(hi));
    return r;
}
__device__ __forceinline__ void unpack2(u64 v, float& lo, float& hi) {
    asm("mov.b64 {%0, %1}, %2;" : "=f"(lo), "=f"(hi) : "l"(v));
}
__device__ __forceinline__ void fma2(u64& d, u64 a, u64 b) {
    asm("fma.rn.f32x2 %0, %1, %2, %0;" : "+l"(d) : "l"(a), "l"(b));
}

// ---------------------------------------------------------------------------
__global__ void k_detect(const void* __restrict__ ei) {
    const long long* p = (const long long*)ei;
    int ok = 1;
    for (int i = 0; i < 128; ++i) {
        long long v = p[i];
        if (v < 0 || v >= NN) { ok = 0; break; }
    }
    g_is64 = ok;
}

__global__ void k_zero_cnt() {
    int i = blockIdx.x * blockDim.x + threadIdx.x;
    if (i < NN) g_cnt[i] = 0;
}

__global__ void k_hist(const void* __restrict__ ei, int nE) {
    int e = blockIdx.x * blockDim.x + threadIdx.x;
    if (e >= nE) return;
    int d = g_is64 ? (int)((const long long*)ei)[nE + e]
                   : ((const int*)ei)[nE + e];
    atomicAdd(&g_cnt[d], 1);
}

__global__ void k_scan1() {
    __shared__ int sh[256];
    int t = threadIdx.x, b = blockIdx.x;
    int i = b * 256 + t;
    int v = (i < NN) ? g_cnt[i] : 0;
    sh[t] = v;
    __syncthreads();
    #pragma unroll
    for (int off = 1; off < 256; off <<= 1) {
        int u = (t >= off) ? sh[t - off] : 0;
        __syncthreads();
        sh[t] += u;
        __syncthreads();
    }
    if (i < NN) g_exc[i] = sh[t] - v;
    if (t == 255) g_bsum[b] = sh[t];
}

__global__ void k_scan2() {
    __shared__ int sh[512];
    int t = threadIdx.x;
    int v = (t < NB) ? g_bsum[t] : 0;
    sh[t] = v;
    __syncthreads();
    #pragma unroll
    for (int off = 1; off < 512; off <<= 1) {
        int u = (t >= off) ? sh[t - off] : 0;
        __syncthreads();
        sh[t] += u;
        __syncthreads();
    }
    g_boff[t] = sh[t] - v;
}

__global__ void k_scan3() {
    int i = blockIdx.x * blockDim.x + threadIdx.x;
    if (i >= NN) return;
    int row = g_exc[i] + g_boff[i >> 8];
    g_rowptr[i] = row;
    g_cur[i] = row;
    g_invdeg[i] = 1.0f / fmaxf((float)g_cnt[i], 1.0f);
}

__global__ void k_fill(const void* __restrict__ ei, int nE) {
    int e = blockIdx.x * blockDim.x + threadIdx.x;
    if (e >= nE) return;
    int s, d;
    if (g_is64) {
        const long long* p = (const long long*)ei;
        s = (int)p[e]; d = (int)p[nE + e];
    } else {
        const int* p = (const int*)ei;
        s = p[e]; d = p[nE + e];
    }
    int pos = atomicAdd(&g_cur[d], 1);
    g_srcs[pos] = s;
}

// ---------------------------------------------------------------------------
// GEMM1: [y1 | self+b1] = x[N,128] @ [W1l | W1r][128,128]
// Tile: 64 rows x 128 cols, K-chunk 32, 256 threads, 4x8 microtile.
// Inner loop in packed f32x2 FMA: 16 FFMA2 per k-step per thread.
// ---------------------------------------------------------------------------
__global__ void k_gemm1(const float* __restrict__ x,
                        const float* __restrict__ Wl,
                        const float* __restrict__ Wr,
                        const float* __restrict__ b) {
    __shared__ float As[32][65];     // [k][m]; scalar reads only (pitch 65)
    __shared__ float Bs[32][128];    // [k][n]; row 512B -> u64 reads aligned

    int tid = threadIdx.x;
    int tx = tid & 15;        // col group: 8 cols (= 4 f32x2 pairs)
    int ty = tid >> 4;        // row group: 4 rows
    int m0 = blockIdx.x * 64;

    u64 acc[4][4] = {};       // [row][colpair], f32x2

    #pragma unroll 1
    for (int c = 0; c < 4; ++c) {
        int kb = c * 32;
        __syncthreads();
        // load A: 64 rows x 32 k ; thread: 2 rows x 4 k
        {
            int kk = (tid & 7) * 4;
            int m  = tid >> 3;
            #pragma unroll
            for (int r = 0; r < 2; ++r, m += 32) {
                int mg = min(m0 + m, NN - 1);
                float4 v = __ldg((const float4*)(x + (size_t)mg * DD + kb + kk));
                As[kk + 0][m] = v.x;
                As[kk + 1][m] = v.y;
                As[kk + 2][m] = v.z;
                As[kk + 3][m] = v.w;
            }
        }
        // load B: 32 k-rows x 128 cols ; thread: 1 row x 16 cols
        {
            int k = tid >> 3;
            int n = (tid & 7) * 16;
            const float* W = (n < 64) ? (Wl + (size_t)(kb + k) * 64 + n)
                                      : (Wr + (size_t)(kb + k) * 64 + (n - 64));
            float4 v0 = __ldg((const float4*)(W));
            float4 v1 = __ldg((const float4*)(W + 4));
            float4 v2 = __ldg((const float4*)(W + 8));
            float4 v3 = __ldg((const float4*)(W + 12));
            *(float4*)&Bs[k][n]      = v0;
            *(float4*)&Bs[k][n + 4]  = v1;
            *(float4*)&Bs[k][n + 8]  = v2;
            *(float4*)&Bs[k][n + 12] = v3;
        }
        __syncthreads();
        #pragma unroll
        for (int k = 0; k < 32; ++k) {
            u64 A2[4];
            #pragma unroll
            for (int i = 0; i < 4; ++i) {
                float a = As[k][ty * 4 + i];
                A2[i] = pack2(a, a);
            }
            const u64* bp = (const u64*)&Bs[k][tx * 8];
            u64 B0 = bp[0], B1 = bp[1], B2 = bp[2], B3 = bp[3];
            #pragma unroll
            for (int i = 0; i < 4; ++i) {
                fma2(acc[i][0], A2[i], B0);
                fma2(acc[i][1], A2[i], B1);
                fma2(acc[i][2], A2[i], B2);
                fma2(acc[i][3], A2[i], B3);
            }
        }
    }

    // epilogue: cols 0..63 -> g_y1 ; cols 64..127 -> g_self (+b1)
    int n = tx * 8;
    bool isSelf = (n >= 64);
    float bb[8];
    #pragma unroll
    for (int j = 0; j < 8; ++j) bb[j] = isSelf ? b[n - 64 + j] : 0.f;
    float* dst = isSelf ? g_self : g_y1;
    int nc = isSelf ? (n - 64) : n;
    #pragma unroll
    for (int i = 0; i < 4; ++i) {
        int mg = m0 + ty * 4 + i;
        if (mg < NN) {
            float o[8];
            #pragma unroll
            for (int j = 0; j < 4; ++j) unpack2(acc[i][j], o[2 * j], o[2 * j + 1]);
            float4 o0, o1;
            o0.x = o[0] + bb[0]; o0.y = o[1] + bb[1];
            o0.z = o[2] + bb[2]; o0.w = o[3] + bb[3];
            o1.x = o[4] + bb[4]; o1.y = o[5] + bb[5];
            o1.z = o[6] + bb[6]; o1.w = o[7] + bb[7];
            *(float4*)(dst + (size_t)mg * HH + nc)     = o0;
            *(float4*)(dst + (size_t)mg * HH + nc + 4) = o1;
        }
    }
}

// ---------------------------------------------------------------------------
// agg1 + ReLU: h[n] = relu( invdeg * sum_{s} y1[s] + self[n] )
// warp per node, lane -> float2.
// ---------------------------------------------------------------------------
__global__ void k_agg1(void) {
    int w = (blockIdx.x * blockDim.x + threadIdx.x) >> 5;
    int lane = threadIdx.x & 31;
    if (w >= NN) return;
    int beg = g_rowptr[w], n = g_cnt[w];
    const float2* yb = (const float2*)g_y1;
    float2 a0 = make_float2(0.f, 0.f), a1 = make_float2(0.f, 0.f);
    int e = 0;
    for (; e + 1 < n; e += 2) {
        int s0 = g_srcs[beg + e];
        int s1 = g_srcs[beg + e + 1];
        float2 v0 = __ldg(yb + (size_t)s0 * 32 + lane);
        float2 v1 = __ldg(yb + (size_t)s1 * 32 + lane);
        a0.x += v0.x; a0.y += v0.y;
        a1.x += v1.x; a1.y += v1.y;
    }
    if (e < n) {
        int s0 = g_srcs[beg + e];
        float2 v0 = __ldg(yb + (size_t)s0 * 32 + lane);
        a0.x += v0.x; a0.y += v0.y;
    }
    float sc = g_invdeg[w];
    float2 s = ((const float2*)g_self)[(size_t)w * 32 + lane];
    float2 o;
    o.x = fmaxf((a0.x + a1.x) * sc + s.x, 0.f);
    o.y = fmaxf((a0.y + a1.y) * sc + s.y, 0.f);
    ((float2*)g_h)[(size_t)w * 32 + lane] = o;
}

// ---------------------------------------------------------------------------
// agg2: g_agg2[n] = invdeg * sum_{s} h[s]   (warp per node, float2 lanes)
// ---------------------------------------------------------------------------
__global__ void k_agg2(void) {
    int w = (blockIdx.x * blockDim.x + threadIdx.x) >> 5;
    int lane = threadIdx.x & 31;
    if (w >= NN) return;
    int beg = g_rowptr[w], n = g_cnt[w];
    const float2* hb = (const float2*)g_h;
    float2 a0 = make_float2(0.f, 0.f), a1 = make_float2(0.f, 0.f);
    int e = 0;
    for (; e + 1 < n; e += 2) {
        int s0 = g_srcs[beg + e];
        int s1 = g_srcs[beg + e + 1];
        float2 v0 = __ldg(hb + (size_t)s0 * 32 + lane);
        float2 v1 = __ldg(hb + (size_t)s1 * 32 + lane);
        a0.x += v0.x; a0.y += v0.y;
        a1.x += v1.x; a1.y += v1.y;
    }
    if (e < n) {
        int s0 = g_srcs[beg + e];
        float2 v0 = __ldg(hb + (size_t)s0 * 32 + lane);
        a0.x += v0.x; a0.y += v0.y;
    }
    float sc = g_invdeg[w];
    float2 o;
    o.x = (a0.x + a1.x) * sc;
    o.y = (a0.y + a1.y) * sc;
    ((float2*)g_agg2)[(size_t)w * 32 + lane] = o;
}

// ---------------------------------------------------------------------------
// GEMM2 + fused log_softmax (warp per node), packed f32x2:
// acc pair = (sum_k agg_k*Wl[k][c], sum_k self_k*Wr[k][c]); z = lo+hi+b.
// Weights interleaved in smem as float2 (Wl, Wr).
// ---------------------------------------------------------------------------
__global__ void k_gemm2(const float* __restrict__ Wl,
                        const float* __restrict__ Wr,
                        const float* __restrict__ b,
                        float* __restrict__ out) {
    __shared__ float2 sW[64 * 40];
    __shared__ float sb[40];
    int tid = threadIdx.x;
    for (int i = tid; i < 64 * 40; i += blockDim.x)
        sW[i] = make_float2(Wl[i], Wr[i]);
    if (tid < 40) sb[tid] = b[tid];
    __syncthreads();

    int w = (blockIdx.x * blockDim.x + tid) >> 5;
    int lane = tid & 31;
    if (w >= NN) return;
    bool lo8 = (lane < 8);

    const float* ag = g_agg2 + (size_t)w * HH;
    const float* hr = g_h    + (size_t)w * HH;
    float a0 = ag[lane], a1 = ag[lane + 32];
    float h0 = hr[lane], h1 = hr[lane + 32];

    u64 acc0 = 0, acc1 = 0;
    #pragma unroll
    for (int k = 0; k < 32; ++k) {
        float av = __shfl_sync(0xffffffffu, a0, k);
        float hv = __shfl_sync(0xffffffffu, h0, k);
        u64 p = pack2(av, hv);
        fma2(acc0, p, *(const u64*)&sW[k * 40 + lane]);
        if (lo8) fma2(acc1, p, *(const u64*)&sW[k * 40 + 32 + lane]);
    }
    #pragma unroll
    for (int k = 0; k < 32; ++k) {
        float av = __shfl_sync(0xffffffffu, a1, k);
        float hv = __shfl_sync(0xffffffffu, h1, k);
        u64 p = pack2(av, hv);
        int kr = k + 32;
        fma2(acc0, p, *(const u64*)&sW[kr * 40 + lane]);
        if (lo8) fma2(acc1, p, *(const u64*)&sW[kr * 40 + 32 + lane]);
    }

    float u0, v0, u1, v1;
    unpack2(acc0, u0, v0);
    unpack2(acc1, u1, v1);
    float z0 = u0 + v0 + sb[lane];
    float z1 = lo8 ? (u1 + v1 + sb[32 + lane]) : -INFINITY;

    float m = fmaxf(z0, z1);
    #pragma unroll
    for (int o = 16; o; o >>= 1) m = fmaxf(m, __shfl_xor_sync(0xffffffffu, m, o));
    float e = expf(z0 - m) + (lo8 ? expf(z1 - m) : 0.f);
    #pragma unroll
    for (int o = 16; o; o >>= 1) e += __shfl_xor_sync(0xffffffffu, e, o);
    float lse = logf(e) + m;

    out[(size_t)w * CC + lane] = z0 - lse;
    if (lo8) out[(size_t)w * CC + 32 + lane] = z1 - lse;
}

// ---------------------------------------------------------------------------
extern "C" void kernel_launch(void* const* d_in, const int* in_sizes, int n_in,
                              void* d_out, int out_size) {
    const float* x   = (const float*)d_in[0];
    const void*  ei  = d_in[1];
    const float* W1l = (const float*)d_in[2];
    const float* W1r = (const float*)d_in[3];
    const float* b1  = (const float*)d_in[4];
    const float* W2l = (const float*)d_in[5];
    const float* W2r = (const float*)d_in[6];
    const float* b2  = (const float*)d_in[7];
    float* out = (float*)d_out;

    int nE = in_sizes[1] / 2;
    int eBlocks = (nE + 255) / 256;
    int nWarpBlocks = (NN * 32 + 255) / 256;

    k_detect<<<1, 1>>>(ei);
    k_zero_cnt<<<(NN + 255) / 256, 256>>>();
    k_hist<<<eBlocks, 256>>>(ei, nE);
    k_scan1<<<NB, 256>>>();
    k_scan2<<<1, 512>>>();
    k_scan3<<<(NN + 255) / 256, 256>>>();
    k_fill<<<eBlocks, 256>>>(ei, nE);

    k_gemm1<<<(NN + 63) / 64, 256>>>(x, W1l, W1r, b1);
    k_agg1<<<nWarpBlocks, 256>>>();
    k_agg2<<<nWarpBlocks, 256>>>();
    k_gemm2<<<(NN + 7) / 8, 256>>>(W2l, W2r, b2, out);
}